// round 15
// baseline (speedup 1.0000x reference)
#include <cuda_runtime.h>
#include <cuda_fp16.h>
#include <math.h>

#define NIMG 24               // B*C = 8*3
#define HH 512
#define WW 512
#define PLANE (HH*WW)
#define EPSC 2e-4f
#define TAU 0.25f
#define TBX 128               // threads per block (4 px/thread/row)
#define RPT 16                // interior rows per block
#define BLOCKS_X (HH/RPT)     // 32 blocks per image
#define W4 (WW/4)             // 128 4-px groups per row
#define SLOTS 12              // staged pt(i) row slots (chunked double-use)
#define SLOT(x) ((x) < SLOTS ? (x) : (x) - SLOTS)

// ---------------- scratch state (static device globals) ---------------------
__device__ __half g_pt[3][NIMG][2][PLANE];      // triple-buffered dual field (fp16)
__device__ float  g_bsum[NIMG][BLOCKS_X][4];    // per-block {dt_i^2, norm_i, dt_j^2, norm_j}
__device__ int    g_cnt[NIMG];                  // arrival counters (self-resetting)
__device__ float  g_Einit[NIMG];
__device__ float  g_Eprev[NIMG];
__device__ int    g_done[NIMG];
__device__ int    g_outbuf[NIMG];               // buffer holding pt used for final out

// ---- approx math (error ~1e-7 rel; budget 1e-3; sqrt.approx(0)=0) -----------
__device__ __forceinline__ float fsqrt_ap(float x) {
    float r; asm("sqrt.approx.f32 %0, %1;" : "=f"(r) : "f"(x)); return r;
}
__device__ __forceinline__ float frcp_ap(float x) {
    float r; asm("rcp.approx.f32 %0, %1;" : "=f"(r) : "f"(x)); return r;
}

// ---- fp16x4 <-> float4 helpers ----------------------------------------------
__device__ __forceinline__ float4 h4f(uint2 u) {
    __half2 a = *reinterpret_cast<__half2*>(&u.x);
    __half2 b = *reinterpret_cast<__half2*>(&u.y);
    float2 fa = __half22float2(a), fb = __half22float2(b);
    return make_float4(fa.x, fa.y, fb.x, fb.y);
}
__device__ __forceinline__ uint2 f4h(float4 f) {
    __half2 a = __floats2half2_rn(f.x, f.y);
    __half2 b = __floats2half2_rn(f.z, f.w);
    uint2 u;
    u.x = *reinterpret_cast<unsigned*>(&a);
    u.y = *reinterpret_cast<unsigned*>(&b);
    return u;
}

// ---- stencil helpers (reference op order) -----------------------------------
__device__ __forceinline__ float4 div4(float4 p0, float4 p1, float4 p0u, float p1l) {
    float4 d;
    d.x = -(p0.x + p1.x) + p0u.x + p1l;
    d.y = -(p0.y + p1.y) + p0u.y + p1.x;
    d.z = -(p0.z + p1.z) + p0u.z + p1.y;
    d.w = -(p0.w + p1.w) + p0u.w + p1.z;
    return d;
}
__device__ __forceinline__ float4 add4(float4 a, float4 b) {
    return make_float4(a.x+b.x, a.y+b.y, a.z+b.z, a.w+b.w);
}
__device__ __forceinline__ float4 sub4(float4 a, float4 b) {
    return make_float4(a.x-b.x, a.y-b.y, a.z-b.z, a.w-b.w);
}
__device__ __forceinline__ float4 zero4() { return make_float4(0,0,0,0); }
__device__ __forceinline__ void tv_upd(float p0, float p1, float g0, float g1,
                                       float tw, float& q0, float& q1, float& rowN) {
    float nm = fsqrt_ap(g0*g0 + g1*g1);
    float rd = frcp_ap(fmaf(tw, nm, 1.0f));
    q0 = (p0 - TAU*g0) * rd;
    q1 = (p1 - TAU*g1) * rd;
    rowN += nm;
}
__device__ __forceinline__ float sum4sq(float4 d) {
    return ((d.x*d.x + d.y*d.y) + d.z*d.z) + d.w*d.w;
}

// ---------------- fused pair kernel: steps (i, i+1) --------------------------
// Chunked staging: phase 2 row j needs only phase-1 rows j..j+2, so 12 slots
// suffice with the schedule P1(k=0..9) | bar | P2(j=0..7) | bar |
// P1(k=10..17 -> slots 10,11,0..5) | bar | P2(j=8..15). Slots 8,9 survive
// untouched for P2b. smem 36.9KB -> 24.7KB => 8 blocks/SM (32 warps) at
// __launch_bounds__(128,8). Numerics identical to full staging (same op order,
// same fp16 round-trip). Last-arriving block makes both convergence decisions.
template<bool FIRST>
__global__ void __launch_bounds__(TBX, 8)
tv_pair_kernel(const float* __restrict__ img,
               const float* __restrict__ weight,
               int rbuf, int sbuf, int tbuf)
{
    __shared__ uint2 s_p0[SLOTS][W4];
    __shared__ uint2 s_p1[SLOTS][W4];
    __shared__ float sred[4][4];
    __shared__ int s_last;

    const int b = blockIdx.y;
    if (!FIRST && g_done[b]) return;

    const int tx   = threadIdx.x;
    const int lane = tx & 31;
    const int c4   = tx * 4;
    const int r0   = blockIdx.x * RPT;
    const bool haveR = (c4 + 4 < WW);

    const float*  __restrict__ imp = img + b * PLANE;
    const float4* __restrict__ im4 = (const float4*)imp;
    const __half* __restrict__ P0h = &g_pt[rbuf][b][0][0];
    const __half* __restrict__ P1h = &g_pt[rbuf][b][1][0];
    const uint2*  __restrict__ P0v = (const uint2*)P0h;
    const uint2*  __restrict__ P1v = (const uint2*)P1h;
    uint2* __restrict__ S0v = (uint2*)&g_pt[sbuf][b][0][0];
    uint2* __restrict__ S1v = (uint2*)&g_pt[sbuf][b][1][0];
    uint2* __restrict__ T0v = (uint2*)&g_pt[tbuf][b][0][0];
    uint2* __restrict__ T1v = (uint2*)&g_pt[tbuf][b][1][0];

    const float wgt = __ldg(&weight[b / 3]);
    const float tw  = TAU / wgt;
    const int  rs   = r0 - 1;

    float ld_i = 0.f, ln_i = 0.f, ld_j = 0.f, ln_j = 0.f;

    // ---- phase-1 rolling state (persists across the two P1 chunks) ----
    float4 p0_cur, p1_cur, dt_cur, out_cur, im_cur;
    if (FIRST) {
        im_cur = (rs >= 0) ? __ldg(&im4[rs * W4 + tx]) : zero4();
        p0_cur = p1_cur = dt_cur = out_cur = zero4();
    } else {
        if (rs >= 0) {
            const int ivs = rs * W4 + tx;
            p0_cur = h4f(__ldcs(&P0v[ivs]));
            p1_cur = h4f(__ldcs(&P1v[ivs]));
            float4 p0u = (rs > 0) ? h4f(__ldcs(&P0v[ivs - W4])) : zero4();
            float p1l = __shfl_up_sync(0xffffffffu, p1_cur.w, 1);
            if (lane == 0) p1l = (c4 > 0) ? __half2float(P1h[rs * WW + c4 - 1]) : 0.f;
            dt_cur = div4(p0_cur, p1_cur, p0u, p1l);
            out_cur = add4(__ldg(&im4[ivs]), dt_cur);
        } else {
            p0_cur = p1_cur = dt_cur = out_cur = zero4();
        }
        im_cur = zero4();   // unused in !FIRST path
    }

    // ---- phase-1 body for one row (k), writing slot SLOT(k) ----
    #define P1_ROW(k)                                                           \
    {                                                                           \
        const int a = rs + (k);                                                 \
        if (a < HH) {                                                           \
            const bool lastrow = (a == HH - 1);                                 \
            const int slot = SLOT(k);                                           \
            float4 q0, q1; float rowN = 0.f;                                    \
            if (FIRST) {                                                        \
                float4 im_nx = zero4();                                         \
                if (!lastrow) im_nx = __ldg(&im4[(a + 1) * W4 + tx]);           \
                float4 g0 = lastrow ? zero4() : sub4(im_nx, im_cur);            \
                float imr = __shfl_down_sync(0xffffffffu, im_cur.x, 1);         \
                if (lane == 31 && haveR && a >= 0) imr = __ldg(&imp[a * WW + c4 + 4]); \
                float4 g1;                                                      \
                g1.x = im_cur.y - im_cur.x;                                     \
                g1.y = im_cur.z - im_cur.y;                                     \
                g1.z = im_cur.w - im_cur.z;                                     \
                g1.w = haveR ? (imr - im_cur.w) : 0.f;                          \
                tv_upd(0.f, 0.f, g0.x, g1.x, tw, q0.x, q1.x, rowN);             \
                tv_upd(0.f, 0.f, g0.y, g1.y, tw, q0.y, q1.y, rowN);             \
                tv_upd(0.f, 0.f, g0.z, g1.z, tw, q0.z, q1.z, rowN);             \
                tv_upd(0.f, 0.f, g0.w, g1.w, tw, q0.w, q1.w, rowN);             \
                im_cur = im_nx;                                                 \
            } else {                                                            \
                float4 p0_nx, p1_nx, dt_nx, out_nx;                             \
                if (!lastrow) {                                                 \
                    const int ivn = (a + 1) * W4 + tx;                          \
                    p0_nx = h4f(__ldcs(&P0v[ivn]));                             \
                    p1_nx = h4f(__ldcs(&P1v[ivn]));                             \
                    float p1ln = __shfl_up_sync(0xffffffffu, p1_nx.w, 1);       \
                    if (lane == 0)                                              \
                        p1ln = (c4 > 0) ? __half2float(P1h[(a + 1) * WW + c4 - 1]) : 0.f; \
                    dt_nx = div4(p0_nx, p1_nx, p0_cur, p1ln);                   \
                    out_nx = add4(__ldg(&im4[ivn]), dt_nx);                     \
                }                                                               \
                float4 g0 = lastrow ? zero4() : sub4(out_nx, out_cur);          \
                float orr = __shfl_down_sync(0xffffffffu, out_cur.x, 1);        \
                if (lane == 31 && haveR && a >= 0) {                            \
                    float q0s = __half2float(P0h[a * WW + c4 + 4]);             \
                    float q1s = __half2float(P1h[a * WW + c4 + 4]);             \
                    float qus = (a > 0) ? __half2float(P0h[(a - 1) * WW + c4 + 4]) : 0.f; \
                    float dtr = -(q0s + q1s) + qus + p1_cur.w;                  \
                    orr = __ldg(&imp[a * WW + c4 + 4]) + dtr;                   \
                }                                                               \
                float4 g1;                                                      \
                g1.x = out_cur.y - out_cur.x;                                   \
                g1.y = out_cur.z - out_cur.y;                                   \
                g1.z = out_cur.w - out_cur.z;                                   \
                g1.w = haveR ? (orr - out_cur.w) : 0.f;                         \
                tv_upd(p0_cur.x, p1_cur.x, g0.x, g1.x, tw, q0.x, q1.x, rowN);   \
                tv_upd(p0_cur.y, p1_cur.y, g0.y, g1.y, tw, q0.y, q1.y, rowN);   \
                tv_upd(p0_cur.z, p1_cur.z, g0.z, g1.z, tw, q0.z, q1.z, rowN);   \
                tv_upd(p0_cur.w, p1_cur.w, g0.w, g1.w, tw, q0.w, q1.w, rowN);   \
                if (!lastrow) { p0_cur = p0_nx; p1_cur = p1_nx;                 \
                                dt_cur = dt_nx; out_cur = out_nx; }             \
            }                                                                   \
            uint2 u0 = f4h(q0), u1 = f4h(q1);                                   \
            if (a >= 0) { s_p0[slot][tx] = u0; s_p1[slot][tx] = u1; }           \
            if ((k) >= 1 && (k) <= RPT) {                                       \
                const int iv = a * W4 + tx;                                     \
                S0v[iv] = u0; S1v[iv] = u1;                                     \
                if (!FIRST) { float4 dte = FIRST ? zero4() : dt_cur; (void)dte; } \
                ln_i += rowN;                                                   \
            }                                                                   \
        }                                                                       \
    }

    // NOTE: ld_i accumulation for !FIRST must use dt of row a BEFORE the roll.
    // The macro above rolls dt_cur at the end; so accumulate ld_i separately
    // inside the !FIRST branch. To keep exact R10 semantics, we re-expand:
    #undef P1_ROW

    // ---- phase-1 row body as a lambda (keeps R10 op order exactly) ----
    auto p1_row = [&](int k) {
        const int a = rs + k;
        if (a >= HH) return;
        const bool lastrow = (a == HH - 1);
        const int slot = SLOT(k);
        float4 q0, q1; float rowN = 0.f;
        float4 dt_here = dt_cur;
        if (FIRST) {
            float4 im_nx = zero4();
            if (!lastrow) im_nx = __ldg(&im4[(a + 1) * W4 + tx]);
            float4 g0 = lastrow ? zero4() : sub4(im_nx, im_cur);
            float imr = __shfl_down_sync(0xffffffffu, im_cur.x, 1);
            if (lane == 31 && haveR && a >= 0) imr = __ldg(&imp[a * WW + c4 + 4]);
            float4 g1;
            g1.x = im_cur.y - im_cur.x;
            g1.y = im_cur.z - im_cur.y;
            g1.z = im_cur.w - im_cur.z;
            g1.w = haveR ? (imr - im_cur.w) : 0.f;
            tv_upd(0.f, 0.f, g0.x, g1.x, tw, q0.x, q1.x, rowN);
            tv_upd(0.f, 0.f, g0.y, g1.y, tw, q0.y, q1.y, rowN);
            tv_upd(0.f, 0.f, g0.z, g1.z, tw, q0.z, q1.z, rowN);
            tv_upd(0.f, 0.f, g0.w, g1.w, tw, q0.w, q1.w, rowN);
            im_cur = im_nx;
            dt_here = zero4();
        } else {
            float4 p0_nx, p1_nx, dt_nx, out_nx;
            if (!lastrow) {
                const int ivn = (a + 1) * W4 + tx;
                p0_nx = h4f(__ldcs(&P0v[ivn]));
                p1_nx = h4f(__ldcs(&P1v[ivn]));
                float p1ln = __shfl_up_sync(0xffffffffu, p1_nx.w, 1);
                if (lane == 0)
                    p1ln = (c4 > 0) ? __half2float(P1h[(a + 1) * WW + c4 - 1]) : 0.f;
                dt_nx = div4(p0_nx, p1_nx, p0_cur, p1ln);
                out_nx = add4(__ldg(&im4[ivn]), dt_nx);
            }
            float4 g0 = lastrow ? zero4() : sub4(out_nx, out_cur);
            float orr = __shfl_down_sync(0xffffffffu, out_cur.x, 1);
            if (lane == 31 && haveR && a >= 0) {
                float q0s = __half2float(P0h[a * WW + c4 + 4]);
                float q1s = __half2float(P1h[a * WW + c4 + 4]);
                float qus = (a > 0) ? __half2float(P0h[(a - 1) * WW + c4 + 4]) : 0.f;
                float dtr = -(q0s + q1s) + qus + p1_cur.w;
                orr = __ldg(&imp[a * WW + c4 + 4]) + dtr;
            }
            float4 g1;
            g1.x = out_cur.y - out_cur.x;
            g1.y = out_cur.z - out_cur.y;
            g1.z = out_cur.w - out_cur.z;
            g1.w = haveR ? (orr - out_cur.w) : 0.f;
            tv_upd(p0_cur.x, p1_cur.x, g0.x, g1.x, tw, q0.x, q1.x, rowN);
            tv_upd(p0_cur.y, p1_cur.y, g0.y, g1.y, tw, q0.y, q1.y, rowN);
            tv_upd(p0_cur.z, p1_cur.z, g0.z, g1.z, tw, q0.z, q1.z, rowN);
            tv_upd(p0_cur.w, p1_cur.w, g0.w, g1.w, tw, q0.w, q1.w, rowN);
            if (!lastrow) { p0_cur = p0_nx; p1_cur = p1_nx; dt_cur = dt_nx; out_cur = out_nx; }
        }
        uint2 u0 = f4h(q0), u1 = f4h(q1);
        if (a >= 0) { s_p0[slot][tx] = u0; s_p1[slot][tx] = u1; }
        if (k >= 1 && k <= RPT) {
            const int iv = a * W4 + tx;
            S0v[iv] = u0; S1v[iv] = u1;
            if (!FIRST) ld_i += sum4sq(dt_here);
            ln_i += rowN;
        }
    };

    // ---- phase-2 rolling state ----
    float4 j_p0, j_p1, j_dt, j_out;

    auto p2_prologue = [&]() {
        j_p0 = h4f(s_p0[1][tx]);
        j_p1 = h4f(s_p1[1][tx]);
        float4 p0u = (r0 > 0) ? h4f(s_p0[0][tx]) : zero4();
        float p1l = __shfl_up_sync(0xffffffffu, j_p1.w, 1);
        if (lane == 0) p1l = (c4 > 0) ? __half2float(((const __half*)s_p1)[1 * WW + c4 - 1]) : 0.f;
        j_dt = div4(j_p0, j_p1, p0u, p1l);
        j_out = add4(__ldg(&im4[r0 * W4 + tx]), j_dt);
    };

    auto p2_row = [&](int j) {
        const __half* sp0h = (const __half*)s_p0;
        const __half* sp1h = (const __half*)s_p1;
        const int r = r0 + j;
        const bool lastrow = (r == HH - 1);
        const int sn  = SLOT(j + 2);   // next row slot
        const int sc  = SLOT(j + 1);   // current row slot (seams)
        const int su  = SLOT(j);       // up row slot (seams)

        float4 p0_nx, p1_nx, dt_nx, out_nx;
        if (!lastrow) {
            p0_nx = h4f(s_p0[sn][tx]);
            p1_nx = h4f(s_p1[sn][tx]);
            float p1ln = __shfl_up_sync(0xffffffffu, p1_nx.w, 1);
            if (lane == 0)
                p1ln = (c4 > 0) ? __half2float(sp1h[sn * WW + c4 - 1]) : 0.f;
            dt_nx = div4(p0_nx, p1_nx, j_p0, p1ln);
            out_nx = add4(__ldg(&im4[(r + 1) * W4 + tx]), dt_nx);
        }

        float4 g0 = lastrow ? zero4() : sub4(out_nx, j_out);
        float orr = __shfl_down_sync(0xffffffffu, j_out.x, 1);
        if (lane == 31 && haveR) {
            float q0s = __half2float(sp0h[sc * WW + c4 + 4]);
            float q1s = __half2float(sp1h[sc * WW + c4 + 4]);
            float qus = (r > 0) ? __half2float(sp0h[su * WW + c4 + 4]) : 0.f;
            float dtr = -(q0s + q1s) + qus + j_p1.w;
            orr = __ldg(&imp[r * WW + c4 + 4]) + dtr;
        }
        float4 g1;
        g1.x = j_out.y - j_out.x;
        g1.y = j_out.z - j_out.y;
        g1.z = j_out.w - j_out.z;
        g1.w = haveR ? (orr - j_out.w) : 0.f;

        float4 q0, q1; float rowN = 0.f;
        tv_upd(j_p0.x, j_p1.x, g0.x, g1.x, tw, q0.x, q1.x, rowN);
        tv_upd(j_p0.y, j_p1.y, g0.y, g1.y, tw, q0.y, q1.y, rowN);
        tv_upd(j_p0.z, j_p1.z, g0.z, g1.z, tw, q0.z, q1.z, rowN);
        tv_upd(j_p0.w, j_p1.w, g0.w, g1.w, tw, q0.w, q1.w, rowN);

        const int iv = r * W4 + tx;
        T0v[iv] = f4h(q0); T1v[iv] = f4h(q1);
        ld_j += sum4sq(j_dt);
        ln_j += rowN;

        if (!lastrow) { j_p0 = p0_nx; j_p1 = p1_nx; j_dt = dt_nx; j_out = out_nx; }
    };

    // ===== chunked schedule =====
    #pragma unroll 2
    for (int k = 0; k < 10; ++k) p1_row(k);         // slots 0..9
    __syncthreads();
    p2_prologue();
    #pragma unroll 2
    for (int j = 0; j < 8; ++j) p2_row(j);          // reads slots 0..9
    __syncthreads();
    #pragma unroll 2
    for (int k = 10; k < RPT + 2; ++k) p1_row(k);   // slots 10,11,0..5
    __syncthreads();
    #pragma unroll 2
    for (int j = 8; j < RPT; ++j) p2_row(j);        // reads slots 8,9,10,11,0..5

    // ===== deterministic block reduction of 4 energy terms =====
    #pragma unroll
    for (int o = 16; o > 0; o >>= 1) {
        ld_i += __shfl_down_sync(0xffffffffu, ld_i, o);
        ln_i += __shfl_down_sync(0xffffffffu, ln_i, o);
        ld_j += __shfl_down_sync(0xffffffffu, ld_j, o);
        ln_j += __shfl_down_sync(0xffffffffu, ln_j, o);
    }
    const int wid = tx >> 5;
    if (lane == 0) { sred[wid][0] = ld_i; sred[wid][1] = ln_i; sred[wid][2] = ld_j; sred[wid][3] = ln_j; }
    __syncthreads();
    if (tx == 0) {
        float a0 = ((sred[0][0] + sred[1][0]) + sred[2][0]) + sred[3][0];
        float a1 = ((sred[0][1] + sred[1][1]) + sred[2][1]) + sred[3][1];
        float a2 = ((sred[0][2] + sred[1][2]) + sred[2][2]) + sred[3][2];
        float a3 = ((sred[0][3] + sred[1][3]) + sred[2][3]) + sred[3][3];
        g_bsum[b][blockIdx.x][0] = a0;
        g_bsum[b][blockIdx.x][1] = a1;
        g_bsum[b][blockIdx.x][2] = a2;
        g_bsum[b][blockIdx.x][3] = a3;
        __threadfence();
        int old = atomicAdd(&g_cnt[b], 1);
        s_last = (old == BLOCKS_X - 1) ? 1 : 0;
    }
    __syncthreads();

    // ===== last-arriving block: cross-block reduce + two convergence decisions
    if (s_last && tx < BLOCKS_X) {
        __threadfence();
        float v0 = g_bsum[b][tx][0];
        float v1 = g_bsum[b][tx][1];
        float v2 = g_bsum[b][tx][2];
        float v3 = g_bsum[b][tx][3];
        #pragma unroll
        for (int o = 16; o > 0; o >>= 1) {
            v0 += __shfl_down_sync(0xffffffffu, v0, o);
            v1 += __shfl_down_sync(0xffffffffu, v1, o);
            v2 += __shfl_down_sync(0xffffffffu, v2, o);
            v3 += __shfl_down_sync(0xffffffffu, v3, o);
        }
        if (tx == 0) {
            float Ei = (v0 + wgt * v1) / (float)PLANE;
            float Ej = (v2 + wgt * v3) / (float)PLANE;
            if (FIRST) {
                g_Einit[b] = Ei;                    // Et(0)
                if (fabsf(Ei - Ej) < EPSC * Ei) {   // conv at step 1
                    g_done[b] = 1; g_outbuf[b] = sbuf;   // entry of step 1 = pt(0)
                } else {
                    g_done[b] = 0; g_Eprev[b] = Ej;
                }
            } else {
                float Einit = g_Einit[b], Eprev = g_Eprev[b];
                if (fabsf(Eprev - Ei) < EPSC * Einit) {        // conv at step i
                    g_done[b] = 1; g_outbuf[b] = rbuf;          // entry = pt(i-1)
                } else if (fabsf(Ei - Ej) < EPSC * Einit) {    // conv at step i+1
                    g_done[b] = 1; g_outbuf[b] = sbuf;          // entry = pt(i)
                } else {
                    g_Eprev[b] = Ej;
                }
            }
            g_cnt[b] = 0;
        }
    }
}

// ---------------- step 8 kernel (single iteration, RPT=16) -------------------
__global__ void __launch_bounds__(TBX, 12)
tv_iter8_kernel(const float* __restrict__ img,
                const float* __restrict__ weight,
                int rbuf, int wbuf)
{
    const int b = blockIdx.y;
    if (g_done[b]) return;

    const int tx   = threadIdx.x;
    const int lane = tx & 31;
    const int c4   = tx * 4;
    const int r0   = blockIdx.x * RPT;
    const bool haveR = (c4 + 4 < WW);

    const float*  __restrict__ imp = img + b * PLANE;
    const float4* __restrict__ im4 = (const float4*)imp;
    const __half* __restrict__ P0h = &g_pt[rbuf][b][0][0];
    const __half* __restrict__ P1h = &g_pt[rbuf][b][1][0];
    const uint2*  __restrict__ P0v = (const uint2*)P0h;
    const uint2*  __restrict__ P1v = (const uint2*)P1h;
    uint2* __restrict__ Q0v = (uint2*)&g_pt[wbuf][b][0][0];
    uint2* __restrict__ Q1v = (uint2*)&g_pt[wbuf][b][1][0];

    const float wgt = __ldg(&weight[b / 3]);
    const float tw  = TAU / wgt;
    const int   i40 = r0 * W4 + tx;

    float ld = 0.f, ln = 0.f;

    float4 p0_cur = h4f(__ldcs(&P0v[i40]));
    float4 p1_cur = h4f(__ldcs(&P1v[i40]));
    float4 p0u = (r0 > 0) ? h4f(__ldcs(&P0v[i40 - W4])) : zero4();
    float p1l = __shfl_up_sync(0xffffffffu, p1_cur.w, 1);
    if (lane == 0) p1l = (c4 > 0) ? __half2float(P1h[r0 * WW + c4 - 1]) : 0.f;
    float4 dt_cur = div4(p0_cur, p1_cur, p0u, p1l);
    float4 out_cur = add4(__ldg(&im4[i40]), dt_cur);

    #pragma unroll 2
    for (int k = 0; k < RPT; ++k) {
        const int r  = r0 + k;
        const int iv = i40 + k * W4;
        const bool lastrow = (r == HH - 1);

        float4 p0_nx, p1_nx, dt_nx, out_nx;
        if (!lastrow) {
            p0_nx = h4f(__ldcs(&P0v[iv + W4]));
            p1_nx = h4f(__ldcs(&P1v[iv + W4]));
            float p1ln = __shfl_up_sync(0xffffffffu, p1_nx.w, 1);
            if (lane == 0)
                p1ln = (c4 > 0) ? __half2float(P1h[(r + 1) * WW + c4 - 1]) : 0.f;
            dt_nx = div4(p0_nx, p1_nx, p0_cur, p1ln);
            out_nx = add4(__ldg(&im4[iv + W4]), dt_nx);
        }

        float4 g0 = lastrow ? zero4() : sub4(out_nx, out_cur);
        float orr = __shfl_down_sync(0xffffffffu, out_cur.x, 1);
        if (lane == 31 && haveR) {
            float q0s = __half2float(P0h[r * WW + c4 + 4]);
            float q1s = __half2float(P1h[r * WW + c4 + 4]);
            float qus = (r > 0) ? __half2float(P0h[(r - 1) * WW + c4 + 4]) : 0.f;
            float dtr = -(q0s + q1s) + qus + p1_cur.w;
            orr = __ldg(&imp[r * WW + c4 + 4]) + dtr;
        }
        float4 g1;
        g1.x = out_cur.y - out_cur.x;
        g1.y = out_cur.z - out_cur.y;
        g1.z = out_cur.w - out_cur.z;
        g1.w = haveR ? (orr - out_cur.w) : 0.f;

        float4 q0, q1; float rowN = 0.f;
        tv_upd(p0_cur.x, p1_cur.x, g0.x, g1.x, tw, q0.x, q1.x, rowN);
        tv_upd(p0_cur.y, p1_cur.y, g0.y, g1.y, tw, q0.y, q1.y, rowN);
        tv_upd(p0_cur.z, p1_cur.z, g0.z, g1.z, tw, q0.z, q1.z, rowN);
        tv_upd(p0_cur.w, p1_cur.w, g0.w, g1.w, tw, q0.w, q1.w, rowN);

        Q0v[iv] = f4h(q0); Q1v[iv] = f4h(q1);
        ld += sum4sq(dt_cur);
        ln += rowN;

        if (!lastrow) { p0_cur = p0_nx; p1_cur = p1_nx; dt_cur = dt_nx; out_cur = out_nx; }
    }

    #pragma unroll
    for (int o = 16; o > 0; o >>= 1) {
        ld += __shfl_down_sync(0xffffffffu, ld, o);
        ln += __shfl_down_sync(0xffffffffu, ln, o);
    }
    __shared__ float sd[4], sn[4];
    __shared__ int s_last;
    const int wid = tx >> 5;
    if (lane == 0) { sd[wid] = ld; sn[wid] = ln; }
    __syncthreads();
    if (tx == 0) {
        float a = ((sd[0] + sd[1]) + sd[2]) + sd[3];
        float n = ((sn[0] + sn[1]) + sn[2]) + sn[3];
        g_bsum[b][blockIdx.x][0] = a;
        g_bsum[b][blockIdx.x][1] = n;
        __threadfence();
        int old = atomicAdd(&g_cnt[b], 1);
        s_last = (old == BLOCKS_X - 1) ? 1 : 0;
    }
    __syncthreads();
    if (s_last && tx < BLOCKS_X) {
        __threadfence();
        float a = g_bsum[b][tx][0];
        float n = g_bsum[b][tx][1];
        #pragma unroll
        for (int o = 16; o > 0; o >>= 1) {
            a += __shfl_down_sync(0xffffffffu, a, o);
            n += __shfl_down_sync(0xffffffffu, n, o);
        }
        if (tx == 0) {
            float Et = (a + wgt * n) / (float)PLANE;
            bool conv = fabsf(g_Eprev[b] - Et) < EPSC * g_Einit[b];
            g_outbuf[b] = conv ? rbuf : wbuf;   // conv@8: out = img+div(pt7); else pt8
            g_cnt[b] = 0;
        }
    }
}

// ---------------- final output: out = img + div(pt[g_outbuf[b]]) -------------
#define FTBY 8
__global__ void __launch_bounds__(TBX * FTBY)
tv_final_kernel(const float* __restrict__ img, float* __restrict__ out)
{
    const int b    = blockIdx.y;
    const int r    = blockIdx.x * FTBY + threadIdx.y;
    const int c4   = threadIdx.x * 4;
    const int idx  = r * WW + c4;
    const int i4   = idx >> 2;
    const int lane = threadIdx.x & 31;

    const int buf = g_outbuf[b];
    const __half* __restrict__ F0h = &g_pt[buf][b][0][0];
    const __half* __restrict__ F1h = &g_pt[buf][b][1][0];
    const uint2*  __restrict__ F0v = (const uint2*)F0h;
    const uint2*  __restrict__ F1v = (const uint2*)F1h;

    float4 p0c = h4f(F0v[i4]);
    float4 p1c = h4f(F1v[i4]);
    float4 p0u = (r > 0) ? h4f(F0v[i4 - W4]) : zero4();
    float p1l = __shfl_up_sync(0xffffffffu, p1c.w, 1);
    if (lane == 0) p1l = (c4 > 0) ? __half2float(F1h[idx - 1]) : 0.f;

    float4 imc = __ldg(&((const float4*)(img + b * PLANE))[i4]);
    float4 o;
    o.x = imc.x + (-(p0c.x + p1c.x) + p0u.x + p1l);
    o.y = imc.y + (-(p0c.y + p1c.y) + p0u.y + p1c.x);
    o.z = imc.z + (-(p0c.z + p1c.z) + p0u.z + p1c.y);
    o.w = imc.w + (-(p0c.w + p1c.w) + p0u.w + p1c.z);
    ((float4*)out)[b * (PLANE/4) + i4] = o;
}

// ---------------- launch ----------------------------------------------------
extern "C" void kernel_launch(void* const* d_in, const int* in_sizes, int n_in,
                              void* d_out, int out_size)
{
    const float* img = (const float*)d_in[0];   // [8,3,512,512] f32
    const float* wgt = (const float*)d_in[1];   // [8] f32
    float* out = (float*)d_out;

    dim3 block(TBX, 1);                         // 128 threads
    dim3 grid(BLOCKS_X, NIMG);                  // 32 x 24 = 768 blocks (one wave @8/SM)

    // steps (0,1): pt0 -> buf0, pt1 -> buf1
    tv_pair_kernel<true ><<<grid, block>>>(img, wgt, 0, 0, 1);
    // steps (2,3): read buf1, pt2 -> buf2, pt3 -> buf0
    tv_pair_kernel<false><<<grid, block>>>(img, wgt, 1, 2, 0);
    // steps (4,5): read buf0, pt4 -> buf1, pt5 -> buf2
    tv_pair_kernel<false><<<grid, block>>>(img, wgt, 0, 1, 2);
    // steps (6,7): read buf2, pt6 -> buf0, pt7 -> buf1
    tv_pair_kernel<false><<<grid, block>>>(img, wgt, 2, 0, 1);
    // step 8: read buf1 (pt7), pt8 -> buf2; outbuf = conv ? 1 : 2
    tv_iter8_kernel<<<grid, block>>>(img, wgt, 1, 2);

    dim3 fblock(TBX, FTBY);                     // 128 x 8
    dim3 fgrid(HH / FTBY, NIMG);                // 64 x 24
    tv_final_kernel<<<fgrid, fblock>>>(img, out);
}

// round 17
// speedup vs baseline: 1.1156x; 1.1156x over previous
#include <cuda_runtime.h>
#include <cuda_fp16.h>
#include <math.h>

#define NIMG 24               // B*C = 8*3
#define HH 512
#define WW 512
#define PLANE (HH*WW)
#define EPSC 2e-4f
#define TAU 0.25f
#define TBX 128               // threads per block (4 px/thread/row)
#define RPT 16                // interior rows per block
#define BLOCKS_X (HH/RPT)     // 32 blocks per image
#define W4 (WW/4)             // 128 4-px groups per row
#define SROWS (RPT+2)         // 18 staged pt(i) rows (1 halo row each side)

// ---------------- scratch state (static device globals) ---------------------
__device__ __half g_pt[3][NIMG][2][PLANE];      // triple-buffered dual field (fp16)
__device__ float  g_bsum[NIMG][BLOCKS_X][4];    // per-block {dt_i^2, norm_i, dt_j^2, norm_j}
__device__ int    g_cnt[NIMG];                  // arrival counters (self-resetting)
__device__ float  g_Einit[NIMG];
__device__ float  g_Eprev[NIMG];
__device__ int    g_done[NIMG];
__device__ int    g_outbuf[NIMG];               // buffer holding pt used for final out

// ---- approx math (error ~1e-7 rel; budget 1e-3; sqrt.approx(0)=0) -----------
__device__ __forceinline__ float fsqrt_ap(float x) {
    float r; asm("sqrt.approx.f32 %0, %1;" : "=f"(r) : "f"(x)); return r;
}
__device__ __forceinline__ float frcp_ap(float x) {
    float r; asm("rcp.approx.f32 %0, %1;" : "=f"(r) : "f"(x)); return r;
}

// ---- fp16x4 <-> float4 helpers ----------------------------------------------
__device__ __forceinline__ float4 h4f(uint2 u) {
    __half2 a = *reinterpret_cast<__half2*>(&u.x);
    __half2 b = *reinterpret_cast<__half2*>(&u.y);
    float2 fa = __half22float2(a), fb = __half22float2(b);
    return make_float4(fa.x, fa.y, fb.x, fb.y);
}
__device__ __forceinline__ uint2 f4h(float4 f) {
    __half2 a = __floats2half2_rn(f.x, f.y);
    __half2 b = __floats2half2_rn(f.z, f.w);
    uint2 u;
    u.x = *reinterpret_cast<unsigned*>(&a);
    u.y = *reinterpret_cast<unsigned*>(&b);
    return u;
}

// ---- stencil helpers (reference op order) -----------------------------------
__device__ __forceinline__ float4 div4(float4 p0, float4 p1, float4 p0u, float p1l) {
    float4 d;
    d.x = -(p0.x + p1.x) + p0u.x + p1l;
    d.y = -(p0.y + p1.y) + p0u.y + p1.x;
    d.z = -(p0.z + p1.z) + p0u.z + p1.y;
    d.w = -(p0.w + p1.w) + p0u.w + p1.z;
    return d;
}
__device__ __forceinline__ float4 add4(float4 a, float4 b) {
    return make_float4(a.x+b.x, a.y+b.y, a.z+b.z, a.w+b.w);
}
__device__ __forceinline__ float4 sub4(float4 a, float4 b) {
    return make_float4(a.x-b.x, a.y-b.y, a.z-b.z, a.w-b.w);
}
__device__ __forceinline__ void tv_upd(float p0, float p1, float g0, float g1,
                                       float tw, float& q0, float& q1, float& rowN) {
    float nm = fsqrt_ap(g0*g0 + g1*g1);
    float rd = frcp_ap(fmaf(tw, nm, 1.0f));
    q0 = (p0 - TAU*g0) * rd;
    q1 = (p1 - TAU*g1) * rd;
    rowN += nm;
}
__device__ __forceinline__ float sum4sq(float4 d) {
    return ((d.x*d.x + d.y*d.y) + d.z*d.z) + d.w*d.w;
}

// ---------------- fused pair kernel: steps (i, i+1) --------------------------
// Phase 1: compute pt(i) for rows r0-1..r0+16 (halo recompute), stage in smem
// (fp16, numerics identical to a global round-trip), write interior to S buf,
// accumulate Et(i) terms over interior. Phase 2: compute pt(i+1) for interior
// rows reading pt(i) from smem, write to T buf, accumulate Et(i+1) terms.
// Last-arriving block makes both convergence decisions in order.
template<bool FIRST>
__global__ void __launch_bounds__(TBX, 6)
tv_pair_kernel(const float* __restrict__ img,
               const float* __restrict__ weight,
               int rbuf, int sbuf, int tbuf)
{
    __shared__ uint2 s_p0[SROWS][W4];
    __shared__ uint2 s_p1[SROWS][W4];
    __shared__ float sred[4][4];
    __shared__ int s_last;

    const int b = blockIdx.y;
    if (!FIRST && g_done[b]) return;

    const int tx   = threadIdx.x;
    const int lane = tx & 31;
    const int c4   = tx * 4;
    const int r0   = blockIdx.x * RPT;
    const bool haveR = (c4 + 4 < WW);

    const float*  __restrict__ imp = img + b * PLANE;
    const float4* __restrict__ im4 = (const float4*)imp;
    const __half* __restrict__ P0h = &g_pt[rbuf][b][0][0];
    const __half* __restrict__ P1h = &g_pt[rbuf][b][1][0];
    const uint2*  __restrict__ P0v = (const uint2*)P0h;
    const uint2*  __restrict__ P1v = (const uint2*)P1h;
    uint2* __restrict__ S0v = (uint2*)&g_pt[sbuf][b][0][0];
    uint2* __restrict__ S1v = (uint2*)&g_pt[sbuf][b][1][0];
    uint2* __restrict__ T0v = (uint2*)&g_pt[tbuf][b][0][0];
    uint2* __restrict__ T1v = (uint2*)&g_pt[tbuf][b][1][0];

    const float wgt = __ldg(&weight[b / 3]);
    const float tw  = TAU / wgt;

    float ld_i = 0.f, ln_i = 0.f, ld_j = 0.f, ln_j = 0.f;

    // ===== phase 1: step i =====
    if (FIRST) {
        // pt(i-1) == 0: out(i) = img, dt_i = 0
        const int rs = r0 - 1;
        float4 im_cur = (rs >= 0) ? __ldg(&im4[rs * W4 + tx]) : make_float4(0,0,0,0);
        #pragma unroll 2
        for (int k = 0; k < SROWS; ++k) {
            const int a = r0 - 1 + k;
            if (a >= HH) break;
            const bool lastrow = (a == HH - 1);
            float4 im_nx = make_float4(0,0,0,0);
            if (!lastrow) im_nx = __ldg(&im4[(a + 1) * W4 + tx]);

            float4 g0 = lastrow ? make_float4(0,0,0,0) : sub4(im_nx, im_cur);
            float imr = __shfl_down_sync(0xffffffffu, im_cur.x, 1);
            if (lane == 31 && haveR && a >= 0) imr = __ldg(&imp[a * WW + c4 + 4]);
            float4 g1;
            g1.x = im_cur.y - im_cur.x;
            g1.y = im_cur.z - im_cur.y;
            g1.z = im_cur.w - im_cur.z;
            g1.w = haveR ? (imr - im_cur.w) : 0.f;

            float4 q0, q1; float rowN = 0.f;
            tv_upd(0.f, 0.f, g0.x, g1.x, tw, q0.x, q1.x, rowN);
            tv_upd(0.f, 0.f, g0.y, g1.y, tw, q0.y, q1.y, rowN);
            tv_upd(0.f, 0.f, g0.z, g1.z, tw, q0.z, q1.z, rowN);
            tv_upd(0.f, 0.f, g0.w, g1.w, tw, q0.w, q1.w, rowN);

            uint2 u0 = f4h(q0), u1 = f4h(q1);
            if (a >= 0) { s_p0[k][tx] = u0; s_p1[k][tx] = u1; }
            if (k >= 1 && k <= RPT) {
                const int iv = a * W4 + tx;
                S0v[iv] = u0; S1v[iv] = u1;
                ln_i += rowN;                  // ld_i stays 0 (dt = 0)
            }
            im_cur = im_nx;
        }
    } else {
        const int rs = r0 - 1;
        float4 p0_cur, p1_cur, dt_cur, out_cur;
        if (rs >= 0) {
            const int ivs = rs * W4 + tx;
            p0_cur = h4f(__ldcs(&P0v[ivs]));
            p1_cur = h4f(__ldcs(&P1v[ivs]));
            float4 p0u = make_float4(0,0,0,0);
            if (rs > 0) p0u = h4f(__ldcs(&P0v[ivs - W4]));
            float p1l = __shfl_up_sync(0xffffffffu, p1_cur.w, 1);
            if (lane == 0) p1l = (c4 > 0) ? __half2float(P1h[rs * WW + c4 - 1]) : 0.f;
            dt_cur = div4(p0_cur, p1_cur, p0u, p1l);
            out_cur = add4(__ldg(&im4[ivs]), dt_cur);
        } else {
            p0_cur = p1_cur = dt_cur = out_cur = make_float4(0,0,0,0);
        }

        #pragma unroll 2
        for (int k = 0; k < SROWS; ++k) {
            const int a = r0 - 1 + k;
            if (a >= HH) break;
            const bool lastrow = (a == HH - 1);

            float4 p0_nx, p1_nx, dt_nx, out_nx;
            if (!lastrow) {
                const int ivn = (a + 1) * W4 + tx;
                p0_nx = h4f(__ldcs(&P0v[ivn]));
                p1_nx = h4f(__ldcs(&P1v[ivn]));
                float p1ln = __shfl_up_sync(0xffffffffu, p1_nx.w, 1);
                if (lane == 0)
                    p1ln = (c4 > 0) ? __half2float(P1h[(a + 1) * WW + c4 - 1]) : 0.f;
                dt_nx = div4(p0_nx, p1_nx, p0_cur, p1ln);
                out_nx = add4(__ldg(&im4[ivn]), dt_nx);
            }

            float4 g0 = lastrow ? make_float4(0,0,0,0) : sub4(out_nx, out_cur);
            float orr = __shfl_down_sync(0xffffffffu, out_cur.x, 1);
            if (lane == 31 && haveR && a >= 0) {
                float q0s = __half2float(P0h[a * WW + c4 + 4]);
                float q1s = __half2float(P1h[a * WW + c4 + 4]);
                float qus = (a > 0) ? __half2float(P0h[(a - 1) * WW + c4 + 4]) : 0.f;
                float dtr = -(q0s + q1s) + qus + p1_cur.w;
                orr = __ldg(&imp[a * WW + c4 + 4]) + dtr;
            }
            float4 g1;
            g1.x = out_cur.y - out_cur.x;
            g1.y = out_cur.z - out_cur.y;
            g1.z = out_cur.w - out_cur.z;
            g1.w = haveR ? (orr - out_cur.w) : 0.f;

            float4 q0, q1; float rowN = 0.f;
            tv_upd(p0_cur.x, p1_cur.x, g0.x, g1.x, tw, q0.x, q1.x, rowN);
            tv_upd(p0_cur.y, p1_cur.y, g0.y, g1.y, tw, q0.y, q1.y, rowN);
            tv_upd(p0_cur.z, p1_cur.z, g0.z, g1.z, tw, q0.z, q1.z, rowN);
            tv_upd(p0_cur.w, p1_cur.w, g0.w, g1.w, tw, q0.w, q1.w, rowN);

            uint2 u0 = f4h(q0), u1 = f4h(q1);
            if (a >= 0) { s_p0[k][tx] = u0; s_p1[k][tx] = u1; }
            if (k >= 1 && k <= RPT) {
                const int iv = a * W4 + tx;
                S0v[iv] = u0; S1v[iv] = u1;
                ld_i += sum4sq(dt_cur);
                ln_i += rowN;
            }
            if (!lastrow) { p0_cur = p0_nx; p1_cur = p1_nx; dt_cur = dt_nx; out_cur = out_nx; }
        }
    }

    __syncthreads();

    // ===== phase 2: step i+1 (pt(i) from smem) =====
    {
        const __half* sp0h = (const __half*)s_p0;
        const __half* sp1h = (const __half*)s_p1;

        float4 p0_cur = h4f(s_p0[1][tx]);
        float4 p1_cur = h4f(s_p1[1][tx]);
        float4 p0u = make_float4(0,0,0,0);
        if (r0 > 0) p0u = h4f(s_p0[0][tx]);
        float p1l = __shfl_up_sync(0xffffffffu, p1_cur.w, 1);
        if (lane == 0) p1l = (c4 > 0) ? __half2float(sp1h[1 * WW + c4 - 1]) : 0.f;
        float4 dt_cur = div4(p0_cur, p1_cur, p0u, p1l);
        float4 out_cur = add4(__ldg(&im4[r0 * W4 + tx]), dt_cur);

        #pragma unroll 2
        for (int j = 0; j < RPT; ++j) {
            const int r = r0 + j;
            const bool lastrow = (r == HH - 1);

            float4 p0_nx, p1_nx, dt_nx, out_nx;
            if (!lastrow) {
                p0_nx = h4f(s_p0[j + 2][tx]);
                p1_nx = h4f(s_p1[j + 2][tx]);
                float p1ln = __shfl_up_sync(0xffffffffu, p1_nx.w, 1);
                if (lane == 0)
                    p1ln = (c4 > 0) ? __half2float(sp1h[(j + 2) * WW + c4 - 1]) : 0.f;
                dt_nx = div4(p0_nx, p1_nx, p0_cur, p1ln);
                out_nx = add4(__ldg(&im4[(r + 1) * W4 + tx]), dt_nx);
            }

            float4 g0 = lastrow ? make_float4(0,0,0,0) : sub4(out_nx, out_cur);
            float orr = __shfl_down_sync(0xffffffffu, out_cur.x, 1);
            if (lane == 31 && haveR) {
                float q0s = __half2float(sp0h[(j + 1) * WW + c4 + 4]);
                float q1s = __half2float(sp1h[(j + 1) * WW + c4 + 4]);
                float qus = (r > 0) ? __half2float(sp0h[j * WW + c4 + 4]) : 0.f;
                float dtr = -(q0s + q1s) + qus + p1_cur.w;
                orr = __ldg(&imp[r * WW + c4 + 4]) + dtr;
            }
            float4 g1;
            g1.x = out_cur.y - out_cur.x;
            g1.y = out_cur.z - out_cur.y;
            g1.z = out_cur.w - out_cur.z;
            g1.w = haveR ? (orr - out_cur.w) : 0.f;

            float4 q0, q1; float rowN = 0.f;
            tv_upd(p0_cur.x, p1_cur.x, g0.x, g1.x, tw, q0.x, q1.x, rowN);
            tv_upd(p0_cur.y, p1_cur.y, g0.y, g1.y, tw, q0.y, q1.y, rowN);
            tv_upd(p0_cur.z, p1_cur.z, g0.z, g1.z, tw, q0.z, q1.z, rowN);
            tv_upd(p0_cur.w, p1_cur.w, g0.w, g1.w, tw, q0.w, q1.w, rowN);

            const int iv = r * W4 + tx;
            T0v[iv] = f4h(q0); T1v[iv] = f4h(q1);
            ld_j += sum4sq(dt_cur);
            ln_j += rowN;

            if (!lastrow) { p0_cur = p0_nx; p1_cur = p1_nx; dt_cur = dt_nx; out_cur = out_nx; }
        }
    }

    // ===== deterministic block reduction of 4 energy terms =====
    #pragma unroll
    for (int o = 16; o > 0; o >>= 1) {
        ld_i += __shfl_down_sync(0xffffffffu, ld_i, o);
        ln_i += __shfl_down_sync(0xffffffffu, ln_i, o);
        ld_j += __shfl_down_sync(0xffffffffu, ld_j, o);
        ln_j += __shfl_down_sync(0xffffffffu, ln_j, o);
    }
    const int wid = tx >> 5;
    if (lane == 0) { sred[wid][0] = ld_i; sred[wid][1] = ln_i; sred[wid][2] = ld_j; sred[wid][3] = ln_j; }
    __syncthreads();
    if (tx == 0) {
        float a0 = ((sred[0][0] + sred[1][0]) + sred[2][0]) + sred[3][0];
        float a1 = ((sred[0][1] + sred[1][1]) + sred[2][1]) + sred[3][1];
        float a2 = ((sred[0][2] + sred[1][2]) + sred[2][2]) + sred[3][2];
        float a3 = ((sred[0][3] + sred[1][3]) + sred[2][3]) + sred[3][3];
        g_bsum[b][blockIdx.x][0] = a0;
        g_bsum[b][blockIdx.x][1] = a1;
        g_bsum[b][blockIdx.x][2] = a2;
        g_bsum[b][blockIdx.x][3] = a3;
        __threadfence();
        int old = atomicAdd(&g_cnt[b], 1);
        s_last = (old == BLOCKS_X - 1) ? 1 : 0;
    }
    __syncthreads();

    // ===== last-arriving block: cross-block reduce + two convergence decisions
    if (s_last && tx < BLOCKS_X) {
        __threadfence();
        float v0 = g_bsum[b][tx][0];
        float v1 = g_bsum[b][tx][1];
        float v2 = g_bsum[b][tx][2];
        float v3 = g_bsum[b][tx][3];
        #pragma unroll
        for (int o = 16; o > 0; o >>= 1) {
            v0 += __shfl_down_sync(0xffffffffu, v0, o);
            v1 += __shfl_down_sync(0xffffffffu, v1, o);
            v2 += __shfl_down_sync(0xffffffffu, v2, o);
            v3 += __shfl_down_sync(0xffffffffu, v3, o);
        }
        if (tx == 0) {
            float Ei = (v0 + wgt * v1) / (float)PLANE;
            float Ej = (v2 + wgt * v3) / (float)PLANE;
            if (FIRST) {
                g_Einit[b] = Ei;                    // Et(0)
                if (fabsf(Ei - Ej) < EPSC * Ei) {   // conv at step 1
                    g_done[b] = 1; g_outbuf[b] = sbuf;   // entry of step 1 = pt(0)
                } else {
                    g_done[b] = 0; g_Eprev[b] = Ej;
                }
            } else {
                float Einit = g_Einit[b], Eprev = g_Eprev[b];
                if (fabsf(Eprev - Ei) < EPSC * Einit) {        // conv at step i
                    g_done[b] = 1; g_outbuf[b] = rbuf;          // entry = pt(i-1)
                } else if (fabsf(Ei - Ej) < EPSC * Einit) {    // conv at step i+1
                    g_done[b] = 1; g_outbuf[b] = sbuf;          // entry = pt(i)
                } else {
                    g_Eprev[b] = Ej;
                }
            }
            g_cnt[b] = 0;
        }
    }
}

// ---------------- step 8 kernel (single iteration, RPT=16) -------------------
// Computes pt(8) and Et(8); decides conv at step 8: outbuf = conv ? pt(7)-buf
// : pt(8)-buf (step 9's dual update / energy are dead work).
__global__ void __launch_bounds__(TBX, 12)
tv_iter8_kernel(const float* __restrict__ img,
                const float* __restrict__ weight,
                int rbuf, int wbuf)
{
    const int b = blockIdx.y;
    if (g_done[b]) return;

    const int tx   = threadIdx.x;
    const int lane = tx & 31;
    const int c4   = tx * 4;
    const int r0   = blockIdx.x * RPT;
    const bool haveR = (c4 + 4 < WW);

    const float*  __restrict__ imp = img + b * PLANE;
    const float4* __restrict__ im4 = (const float4*)imp;
    const __half* __restrict__ P0h = &g_pt[rbuf][b][0][0];
    const __half* __restrict__ P1h = &g_pt[rbuf][b][1][0];
    const uint2*  __restrict__ P0v = (const uint2*)P0h;
    const uint2*  __restrict__ P1v = (const uint2*)P1h;
    uint2* __restrict__ Q0v = (uint2*)&g_pt[wbuf][b][0][0];
    uint2* __restrict__ Q1v = (uint2*)&g_pt[wbuf][b][1][0];

    const float wgt = __ldg(&weight[b / 3]);
    const float tw  = TAU / wgt;
    const int   i40 = r0 * W4 + tx;

    float ld = 0.f, ln = 0.f;

    float4 p0_cur = h4f(__ldcs(&P0v[i40]));
    float4 p1_cur = h4f(__ldcs(&P1v[i40]));
    float4 p0u = make_float4(0,0,0,0);
    if (r0 > 0) p0u = h4f(__ldcs(&P0v[i40 - W4]));
    float p1l = __shfl_up_sync(0xffffffffu, p1_cur.w, 1);
    if (lane == 0) p1l = (c4 > 0) ? __half2float(P1h[r0 * WW + c4 - 1]) : 0.f;
    float4 dt_cur = div4(p0_cur, p1_cur, p0u, p1l);
    float4 out_cur = add4(__ldg(&im4[i40]), dt_cur);

    #pragma unroll 2
    for (int k = 0; k < RPT; ++k) {
        const int r  = r0 + k;
        const int iv = i40 + k * W4;
        const bool lastrow = (r == HH - 1);

        float4 p0_nx, p1_nx, dt_nx, out_nx;
        if (!lastrow) {
            p0_nx = h4f(__ldcs(&P0v[iv + W4]));
            p1_nx = h4f(__ldcs(&P1v[iv + W4]));
            float p1ln = __shfl_up_sync(0xffffffffu, p1_nx.w, 1);
            if (lane == 0)
                p1ln = (c4 > 0) ? __half2float(P1h[(r + 1) * WW + c4 - 1]) : 0.f;
            dt_nx = div4(p0_nx, p1_nx, p0_cur, p1ln);
            out_nx = add4(__ldg(&im4[iv + W4]), dt_nx);
        }

        float4 g0 = lastrow ? make_float4(0,0,0,0) : sub4(out_nx, out_cur);
        float orr = __shfl_down_sync(0xffffffffu, out_cur.x, 1);
        if (lane == 31 && haveR) {
            float q0s = __half2float(P0h[r * WW + c4 + 4]);
            float q1s = __half2float(P1h[r * WW + c4 + 4]);
            float qus = (r > 0) ? __half2float(P0h[(r - 1) * WW + c4 + 4]) : 0.f;
            float dtr = -(q0s + q1s) + qus + p1_cur.w;
            orr = __ldg(&imp[r * WW + c4 + 4]) + dtr;
        }
        float4 g1;
        g1.x = out_cur.y - out_cur.x;
        g1.y = out_cur.z - out_cur.y;
        g1.z = out_cur.w - out_cur.z;
        g1.w = haveR ? (orr - out_cur.w) : 0.f;

        float4 q0, q1; float rowN = 0.f;
        tv_upd(p0_cur.x, p1_cur.x, g0.x, g1.x, tw, q0.x, q1.x, rowN);
        tv_upd(p0_cur.y, p1_cur.y, g0.y, g1.y, tw, q0.y, q1.y, rowN);
        tv_upd(p0_cur.z, p1_cur.z, g0.z, g1.z, tw, q0.z, q1.z, rowN);
        tv_upd(p0_cur.w, p1_cur.w, g0.w, g1.w, tw, q0.w, q1.w, rowN);

        Q0v[iv] = f4h(q0); Q1v[iv] = f4h(q1);
        ld += sum4sq(dt_cur);
        ln += rowN;

        if (!lastrow) { p0_cur = p0_nx; p1_cur = p1_nx; dt_cur = dt_nx; out_cur = out_nx; }
    }

    #pragma unroll
    for (int o = 16; o > 0; o >>= 1) {
        ld += __shfl_down_sync(0xffffffffu, ld, o);
        ln += __shfl_down_sync(0xffffffffu, ln, o);
    }
    __shared__ float sd[4], sn[4];
    __shared__ int s_last;
    const int wid = tx >> 5;
    if (lane == 0) { sd[wid] = ld; sn[wid] = ln; }
    __syncthreads();
    if (tx == 0) {
        float a = ((sd[0] + sd[1]) + sd[2]) + sd[3];
        float n = ((sn[0] + sn[1]) + sn[2]) + sn[3];
        g_bsum[b][blockIdx.x][0] = a;
        g_bsum[b][blockIdx.x][1] = n;
        __threadfence();
        int old = atomicAdd(&g_cnt[b], 1);
        s_last = (old == BLOCKS_X - 1) ? 1 : 0;
    }
    __syncthreads();
    if (s_last && tx < BLOCKS_X) {
        __threadfence();
        float a = g_bsum[b][tx][0];
        float n = g_bsum[b][tx][1];
        #pragma unroll
        for (int o = 16; o > 0; o >>= 1) {
            a += __shfl_down_sync(0xffffffffu, a, o);
            n += __shfl_down_sync(0xffffffffu, n, o);
        }
        if (tx == 0) {
            float Et = (a + wgt * n) / (float)PLANE;
            bool conv = fabsf(g_Eprev[b] - Et) < EPSC * g_Einit[b];
            g_outbuf[b] = conv ? rbuf : wbuf;   // conv@8: out = img+div(pt7); else pt8
            g_cnt[b] = 0;
        }
    }
}

// ---------------- final output: out = img + div(pt[g_outbuf[b]]) -------------
#define FTBY 8
__global__ void __launch_bounds__(TBX * FTBY)
tv_final_kernel(const float* __restrict__ img, float* __restrict__ out)
{
    const int b    = blockIdx.y;
    const int r    = blockIdx.x * FTBY + threadIdx.y;
    const int c4   = threadIdx.x * 4;
    const int idx  = r * WW + c4;
    const int i4   = idx >> 2;
    const int lane = threadIdx.x & 31;

    const int buf = g_outbuf[b];
    const __half* __restrict__ F0h = &g_pt[buf][b][0][0];
    const __half* __restrict__ F1h = &g_pt[buf][b][1][0];
    const uint2*  __restrict__ F0v = (const uint2*)F0h;
    const uint2*  __restrict__ F1v = (const uint2*)F1h;

    float4 p0c = h4f(F0v[i4]);
    float4 p1c = h4f(F1v[i4]);
    float4 p0u = (r > 0) ? h4f(F0v[i4 - W4]) : make_float4(0,0,0,0);
    float p1l = __shfl_up_sync(0xffffffffu, p1c.w, 1);
    if (lane == 0) p1l = (c4 > 0) ? __half2float(F1h[idx - 1]) : 0.f;

    float4 imc = __ldg(&((const float4*)(img + b * PLANE))[i4]);
    float4 o;
    o.x = imc.x + (-(p0c.x + p1c.x) + p0u.x + p1l);
    o.y = imc.y + (-(p0c.y + p1c.y) + p0u.y + p1c.x);
    o.z = imc.z + (-(p0c.z + p1c.z) + p0u.z + p1c.y);
    o.w = imc.w + (-(p0c.w + p1c.w) + p0u.w + p1c.z);
    ((float4*)out)[b * (PLANE/4) + i4] = o;
}

// ---------------- launch ----------------------------------------------------
extern "C" void kernel_launch(void* const* d_in, const int* in_sizes, int n_in,
                              void* d_out, int out_size)
{
    const float* img = (const float*)d_in[0];   // [8,3,512,512] f32
    const float* wgt = (const float*)d_in[1];   // [8] f32
    float* out = (float*)d_out;

    dim3 block(TBX, 1);                         // 128 threads
    dim3 grid(BLOCKS_X, NIMG);                  // 32 x 24 = 768 blocks (one wave @6/SM)

    // steps (0,1): pt0 -> buf0, pt1 -> buf1
    tv_pair_kernel<true ><<<grid, block>>>(img, wgt, 0, 0, 1);
    // steps (2,3): read buf1, pt2 -> buf2, pt3 -> buf0
    tv_pair_kernel<false><<<grid, block>>>(img, wgt, 1, 2, 0);
    // steps (4,5): read buf0, pt4 -> buf1, pt5 -> buf2
    tv_pair_kernel<false><<<grid, block>>>(img, wgt, 0, 1, 2);
    // steps (6,7): read buf2, pt6 -> buf0, pt7 -> buf1
    tv_pair_kernel<false><<<grid, block>>>(img, wgt, 2, 0, 1);
    // step 8: read buf1 (pt7), pt8 -> buf2; outbuf = conv ? 1 : 2
    tv_iter8_kernel<<<grid, block>>>(img, wgt, 1, 2);

    dim3 fblock(TBX, FTBY);                     // 128 x 8
    dim3 fgrid(HH / FTBY, NIMG);                // 64 x 24
    tv_final_kernel<<<fgrid, fblock>>>(img, out);
}